// round 10
// baseline (speedup 1.0000x reference)
#include <cuda_runtime.h>
#include <cstdint>

#define B_   16
#define N_   1024
#define M_   12
#define FB_  32
#define F_   128
#define ROWS_TOT (B_ * N_)   // 16384

__device__ float g_p[ROWS_TOT];
__device__ float g_s[ROWS_TOT];

static __device__ __forceinline__ void fma2(uint64_t& a, uint64_t u, uint64_t v) {
    asm("fma.rn.f32x2 %0, %1, %2, %0;" : "+l"(a) : "l"(u), "l"(v));
}
static __device__ __forceinline__ float2 upk(uint64_t d) {
    float2 f; asm("mov.b64 {%0, %1}, %2;" : "=f"(f.x), "=f"(f.y) : "l"(d)); return f;
}

// ---------------------------------------------------------------------------
// Kernel 1: coalesced, shuffle-free bond statistic.
//   Block: 384 threads, 32 rows (= 384 m-vectors = 3072 float4s).
//   Phase 1: coalesced float4 sq-sums -> sP[3072]
//   Phase 2: 384 threads fold 8 partials -> r = 1/||v||^2 -> sR[384]
//   Phase 3: 32 threads fold 12 r's -> p
// ---------------------------------------------------------------------------
__global__ __launch_bounds__(384) void bond_kernel(const float* __restrict__ bond) {
    __shared__ float sP[3072];
    __shared__ float sR[384];
    int tid = threadIdx.x;
    const float4* base = (const float4*)(bond + (size_t)blockIdx.x * (32 * M_ * FB_));

#pragma unroll
    for (int it = 0; it < 8; ++it) {
        float4 v = base[it * 384 + tid];
        sP[it * 384 + tid] = v.x*v.x + v.y*v.y + v.z*v.z + v.w*v.w;
    }
    __syncthreads();

    {
        float4 p0 = ((const float4*)sP)[tid * 2];
        float4 p1 = ((const float4*)sP)[tid * 2 + 1];
        float s = p0.x + p0.y + p0.z + p0.w + p1.x + p1.y + p1.z + p1.w;
        sR[tid] = 1.0f / s;                  // (sqrt(s))^-2 == 1/s
    }
    __syncthreads();

    if (tid < 32) {
        float sum = 0.f, prod = 1.f;
#pragma unroll
        for (int m = 0; m < M_; ++m) {
            float r = sR[tid * M_ + m];
            sum += r; prod *= r;
        }
        float D  = fmaxf(sum, 1e-12f);
        float d2 = D * D, d4 = d2 * d2;
        g_p[blockIdx.x * 32 + tid] = prod / (d4 * d4 * d4);
    }
}

// ---------------------------------------------------------------------------
// Kernel 2: colsum over B, u = max(colsum,eps)/p, s = u / sum_n u
// ---------------------------------------------------------------------------
__global__ void s_kernel() {
    __shared__ float red[32];
    int b = blockIdx.x, n = threadIdx.x;
    int wid = n >> 5, lane = n & 31;

    float cs = 0.f;
#pragma unroll
    for (int bb = 0; bb < B_; ++bb) cs += g_p[bb * N_ + n];
    float u = fmaxf(cs, 1e-12f) / g_p[b * N_ + n];

    float v = u;
#pragma unroll
    for (int off = 16; off; off >>= 1) v += __shfl_xor_sync(0xffffffffu, v, off);
    if (lane == 0) red[wid] = v;
    __syncthreads();
    if (wid == 0) {
        float t = red[lane];
#pragma unroll
        for (int off = 16; off; off >>= 1) t += __shfl_xor_sync(0xffffffffu, t, off);
        if (lane == 0) red[0] = 1.0f / fmaxf(t, 1e-12f);
    }
    __syncthreads();
    g_s[b * N_ + n] = u * red[0];
}

// ---------------------------------------------------------------------------
// Kernel 3: fused gather + mean + scale + GEMM + bias + ReLU
//   512 blocks x 256 threads, 32 rows each. smem 48 KB (sA2 dup 32 + sW 16).
//   Microtile 4 rows x 4 cols. A stored as duplicated (a,a) pairs so both
//   operands of fma.rn.f32x2 come straight from LDS.128 — no packing MOVs.
// ---------------------------------------------------------------------------
__global__ __launch_bounds__(256, 3) void fused_kernel(
    const float* __restrict__ atom, const int* __restrict__ adj,
    const float* __restrict__ W, const float* __restrict__ bias,
    float* __restrict__ out)
{
    __shared__ float sA2[32 * 256];    // 32 KB: row-major, row stride 256 floats
    __shared__ float sW[32 * F_];      // 16 KB: current K-chunk

    int tid  = threadIdx.x;
    int wid  = tid >> 5;
    int lane = tid & 31;
    int row0 = blockIdx.x << 5;

    // ---- Build A tile: each warp produces 4 rows (scaled by s), dup pairs ----
#pragma unroll
    for (int rr = 0; rr < 4; ++rr) {
        int r = (wid << 2) + rr;
        int g = row0 + r;
        int b = g >> 10;
        const float* arow  = atom + ((size_t)g << 7);
        const float* abase = atom + ((size_t)b << 17);
        int myidx = (lane < M_) ? adj[(size_t)g * M_ + lane] : 0;

        float4 self = *(const float4*)(arow + (lane << 2));
        float ax = 0.f, ay = 0.f, az = 0.f, aw = 0.f;
#pragma unroll
        for (int m = 0; m < M_; ++m) {
            int idx = __shfl_sync(0xffffffffu, myidx, m) & (N_ - 1);
            float4 nb = *(const float4*)(abase + ((size_t)idx << 7) + (lane << 2));
            ax += nb.x; ay += nb.y; az += nb.z; aw += nb.w;
        }
        float sc = g_s[g];
        const float inv12 = 1.0f / 12.0f;
        float vx = (self.x + ax * inv12) * sc;
        float vy = (self.y + ay * inv12) * sc;
        float vz = (self.z + az * inv12) * sc;
        float vw = (self.w + aw * inv12) * sc;
        float4* dst = (float4*)&sA2[r * 256 + (lane << 3)];
        dst[0] = make_float4(vx, vx, vy, vy);
        dst[1] = make_float4(vz, vz, vw, vw);
    }

    // ---- GEMM: 4 rows x 4 cols per thread ----
    uint64_t acc[4][2];
#pragma unroll
    for (int r = 0; r < 4; ++r) { acc[r][0] = 0ull; acc[r][1] = 0ull; }

#pragma unroll
    for (int kc = 0; kc < 4; ++kc) {
        __syncthreads();               // drain readers of sW (covers sA2 build on kc==0)
        {
            const float4* src = (const float4*)(W + (size_t)(kc << 5) * F_);
            float4* dstw = (float4*)sW;
#pragma unroll
            for (int t = 0; t < 4; ++t) dstw[tid + (t << 8)] = src[tid + (t << 8)];
        }
        __syncthreads();

#pragma unroll
        for (int k4 = 0; k4 < 8; ++k4) {
            // W rows k4*4..k4*4+3 of this chunk, lane's 4 cols, as u64 pairs
            ulonglong2 wv[4];
#pragma unroll
            for (int q = 0; q < 4; ++q)
                wv[q] = *(const ulonglong2*)&sW[((k4 << 2) + q) * F_ + (lane << 2)];
#pragma unroll
            for (int r = 0; r < 4; ++r) {
                const ulonglong2* ap = (const ulonglong2*)
                    &sA2[((wid << 2) + r) * 256 + (kc << 6) + (k4 << 3)];
                ulonglong2 a01 = ap[0];   // (a,a) for k4*4+0 and +1
                ulonglong2 a23 = ap[1];   // (a,a) for k4*4+2 and +3
                fma2(acc[r][0], a01.x, wv[0].x);
                fma2(acc[r][1], a01.x, wv[0].y);
                fma2(acc[r][0], a01.y, wv[1].x);
                fma2(acc[r][1], a01.y, wv[1].y);
                fma2(acc[r][0], a23.x, wv[2].x);
                fma2(acc[r][1], a23.x, wv[2].y);
                fma2(acc[r][0], a23.y, wv[3].x);
                fma2(acc[r][1], a23.y, wv[3].y);
            }
        }
    }

    // ---- Epilogue: bias + ReLU ----
    float4 bv = *(const float4*)(bias + (lane << 2));
#pragma unroll
    for (int r = 0; r < 4; ++r) {
        int g = row0 + (wid << 2) + r;
        float2 lo = upk(acc[r][0]);
        float2 hi = upk(acc[r][1]);
        float4 o;
        o.x = fmaxf(lo.x + bv.x, 0.f);
        o.y = fmaxf(lo.y + bv.y, 0.f);
        o.z = fmaxf(hi.x + bv.z, 0.f);
        o.w = fmaxf(hi.y + bv.w, 0.f);
        *(float4*)(out + ((size_t)g << 7) + (lane << 2)) = o;
    }
}

// ---------------------------------------------------------------------------
extern "C" void kernel_launch(void* const* d_in, const int* in_sizes, int n_in,
                              void* d_out, int out_size) {
    const float* atom = (const float*)d_in[0];
    const float* bond = (const float*)d_in[1];
    const int*   adj  = (const int*)d_in[2];
    const float* W    = (const float*)d_in[3];
    const float* bias = (const float*)d_in[4];
    float*       out  = (float*)d_out;

    bond_kernel <<<ROWS_TOT / 32, 384>>>(bond);
    s_kernel    <<<B_, 1024>>>();
    fused_kernel<<<ROWS_TOT / 32, 256>>>(atom, adj, W, bias, out);
}

// round 11
// speedup vs baseline: 1.7440x; 1.7440x over previous
#include <cuda_runtime.h>
#include <cstdint>

#define B_   16
#define N_   1024
#define M_   12
#define FB_  32
#define F_   128
#define ROWS_TOT (B_ * N_)   // 16384

__device__ float g_p[ROWS_TOT];
__device__ float g_s[ROWS_TOT];
__device__ float g_Y[ROWS_TOT * F_];   // unscaled GEMM result (8 MB, L2-resident)

// ---------------------------------------------------------------------------
// Kernel 1 (R4-proven): p[b,n] = prod_m r_m / max(sum_m r_m,eps)^12
// One warp per TWO rows (6 independent LDG.128 per thread).
// ---------------------------------------------------------------------------
__global__ void bond_kernel(const float* __restrict__ bond) {
    int warp = (blockIdx.x << 3) + (threadIdx.x >> 5);
    int lane = threadIdx.x & 31;
    int grp  = lane >> 3;
    int sub  = lane & 7;
    int row0 = warp << 1;
    const float* b0 = bond + (size_t)row0 * (M_ * FB_);
    const float* b1 = b0 + (M_ * FB_);

    float4 v0[3], v1[3];
#pragma unroll
    for (int i = 0; i < 3; ++i) {
        int off = (((i << 2) + grp) << 5) + (sub << 2);
        v0[i] = *(const float4*)(b0 + off);
        v1[i] = *(const float4*)(b1 + off);
    }

    float sum0 = 0.f, prod0 = 1.f, sum1 = 0.f, prod1 = 1.f;
#pragma unroll
    for (int i = 0; i < 3; ++i) {
        float s0 = v0[i].x*v0[i].x + v0[i].y*v0[i].y + v0[i].z*v0[i].z + v0[i].w*v0[i].w;
        float s1 = v1[i].x*v1[i].x + v1[i].y*v1[i].y + v1[i].z*v1[i].z + v1[i].w*v1[i].w;
#pragma unroll
        for (int off = 1; off <= 4; off <<= 1) {
            s0 += __shfl_xor_sync(0xffffffffu, s0, off);
            s1 += __shfl_xor_sync(0xffffffffu, s1, off);
        }
        float r0 = 1.0f / s0;          // (sqrt(s))^-2 == 1/s
        float r1 = 1.0f / s1;
        sum0 += r0; prod0 *= r0;
        sum1 += r1; prod1 *= r1;
    }
#pragma unroll
    for (int off = 8; off <= 16; off <<= 1) {
        sum0  += __shfl_xor_sync(0xffffffffu, sum0, off);
        sum1  += __shfl_xor_sync(0xffffffffu, sum1, off);
        prod0 *= __shfl_xor_sync(0xffffffffu, prod0, off);
        prod1 *= __shfl_xor_sync(0xffffffffu, prod1, off);
    }
    if (lane == 0) {
        float D  = fmaxf(sum0, 1e-12f);
        float d2 = D*D, d4 = d2*d2;
        g_p[row0] = prod0 / (d4*d4*d4);
    } else if (lane == 1) {
        float D  = fmaxf(sum1, 1e-12f);
        float d2 = D*D, d4 = d2*d2;
        g_p[row0 + 1] = prod1 / (d4*d4*d4);
    }
}

// ---------------------------------------------------------------------------
// Kernel 2 (proven): colsum over B, u = max(colsum,eps)/p, s = u / sum_n u
// ---------------------------------------------------------------------------
__global__ void s_kernel() {
    __shared__ float red[32];
    int b = blockIdx.x, n = threadIdx.x;
    int wid = n >> 5, lane = n & 31;

    float cs = 0.f;
#pragma unroll
    for (int bb = 0; bb < B_; ++bb) cs += g_p[bb * N_ + n];
    float u = fmaxf(cs, 1e-12f) / g_p[b * N_ + n];

    float v = u;
#pragma unroll
    for (int off = 16; off; off >>= 1) v += __shfl_xor_sync(0xffffffffu, v, off);
    if (lane == 0) red[wid] = v;
    __syncthreads();
    if (wid == 0) {
        float t = red[lane];
#pragma unroll
        for (int off = 16; off; off >>= 1) t += __shfl_xor_sync(0xffffffffu, t, off);
        if (lane == 0) red[0] = 1.0f / fmaxf(t, 1e-12f);
    }
    __syncthreads();
    g_s[b * N_ + n] = u * red[0];
}

// ---------------------------------------------------------------------------
// Kernel 3 (R4-proven skeleton, s removed): gather + mean + GEMM -> Y
//   256 blocks x 256 threads, 64 rows, microtile 8x4, packed f32x2.
// ---------------------------------------------------------------------------
__global__ __launch_bounds__(256) void fusedY_kernel(
    const float* __restrict__ atom, const int* __restrict__ adj,
    const float* __restrict__ W)
{
    __shared__ float sA[64][F_];       // 32 KB
    __shared__ float sW[32][F_];       // 16 KB

    int tid  = threadIdx.x;
    int wid  = tid >> 5;
    int lane = tid & 31;
    int row0 = blockIdx.x << 6;

#pragma unroll
    for (int rr = 0; rr < 8; ++rr) {
        int r = (wid << 3) + rr;
        int g = row0 + r;
        int b = g >> 10;
        const float* arow  = atom + ((size_t)g << 7);
        const float* abase = atom + ((size_t)b << 17);
        int myidx = (lane < M_) ? adj[(size_t)g * M_ + lane] : 0;

        float4 self = *(const float4*)(arow + (lane << 2));
        float ax = 0.f, ay = 0.f, az = 0.f, aw = 0.f;
#pragma unroll
        for (int m = 0; m < M_; ++m) {
            int idx = __shfl_sync(0xffffffffu, myidx, m) & (N_ - 1);
            float4 nb = *(const float4*)(abase + ((size_t)idx << 7) + (lane << 2));
            ax += nb.x; ay += nb.y; az += nb.z; aw += nb.w;
        }
        const float inv12 = 1.0f / 12.0f;
        float4 av;
        av.x = self.x + ax * inv12;
        av.y = self.y + ay * inv12;
        av.z = self.z + az * inv12;
        av.w = self.w + aw * inv12;
        *(float4*)&sA[r][lane << 2] = av;
    }

    unsigned long long acc[8][2];
#pragma unroll
    for (int r = 0; r < 8; ++r) { acc[r][0] = 0ull; acc[r][1] = 0ull; }

#pragma unroll
    for (int kc = 0; kc < 4; ++kc) {
        __syncthreads();               // covers A-build on kc==0, sW readers after
        {
            const float4* src = (const float4*)(W + (size_t)(kc << 5) * F_);
            float4* dst = (float4*)sW;
#pragma unroll
            for (int t = 0; t < 4; ++t) dst[tid + (t << 8)] = src[tid + (t << 8)];
        }
        __syncthreads();

        int kb = kc << 5;
#pragma unroll
        for (int kk = 0; kk < 32; ++kk) {
            const unsigned long long* wp =
                (const unsigned long long*)&sW[kk][lane << 2];
            unsigned long long w01 = wp[0], w23 = wp[1];
#pragma unroll
            for (int r = 0; r < 8; ++r) {
                float a = sA[(wid << 3) + r][kb + kk];   // warp-broadcast LDS
                unsigned long long a2;
                asm("mov.b64 %0, {%1, %1};" : "=l"(a2) : "f"(a));
                asm("fma.rn.f32x2 %0, %1, %2, %0;" : "+l"(acc[r][0]) : "l"(a2), "l"(w01));
                asm("fma.rn.f32x2 %0, %1, %2, %0;" : "+l"(acc[r][1]) : "l"(a2), "l"(w23));
            }
        }
    }

#pragma unroll
    for (int r = 0; r < 8; ++r) {
        int g = row0 + (wid << 3) + r;
        float c0, c1, c2, c3;
        asm("mov.b64 {%0, %1}, %2;" : "=f"(c0), "=f"(c1) : "l"(acc[r][0]));
        asm("mov.b64 {%0, %1}, %2;" : "=f"(c2), "=f"(c3) : "l"(acc[r][1]));
        *(float4*)(g_Y + ((size_t)g << 7) + (lane << 2)) = make_float4(c0, c1, c2, c3);
    }
}

// ---------------------------------------------------------------------------
// Kernel 4 (proven): out = relu(s*Y + bias)
// ---------------------------------------------------------------------------
__global__ __launch_bounds__(256) void epilogue_kernel(
    const float* __restrict__ bias, float* __restrict__ out)
{
    int idx = blockIdx.x * 256 + threadIdx.x;      // float4 index, 524288 total
    int row = idx >> 5;
    int c4  = idx & 31;
    float s = g_s[row];
    float4 y  = *(const float4*)(g_Y + ((size_t)idx << 2));
    float4 bv = *(const float4*)(bias + (c4 << 2));
    float4 o;
    o.x = fmaxf(fmaf(s, y.x, bv.x), 0.f);
    o.y = fmaxf(fmaf(s, y.y, bv.y), 0.f);
    o.z = fmaxf(fmaf(s, y.z, bv.z), 0.f);
    o.w = fmaxf(fmaf(s, y.w, bv.w), 0.f);
    *(float4*)(out + ((size_t)idx << 2)) = o;
}

// ---------------------------------------------------------------------------
// Launch: fork-join graph.
//   legacy:  fusedY ────────────────┐
//   side:    bond → s ──────────────┤→ epilogue (legacy)
// ---------------------------------------------------------------------------
extern "C" void kernel_launch(void* const* d_in, const int* in_sizes, int n_in,
                              void* d_out, int out_size) {
    const float* atom = (const float*)d_in[0];
    const float* bond = (const float*)d_in[1];
    const int*   adj  = (const int*)d_in[2];
    const float* W    = (const float*)d_in[3];
    const float* bias = (const float*)d_in[4];
    float*       out  = (float*)d_out;

    static cudaStream_t s_side = nullptr;
    static cudaEvent_t  ev_fork = nullptr, ev_join = nullptr;
    if (!s_side) {
        cudaStreamCreateWithFlags(&s_side, cudaStreamNonBlocking);
        cudaEventCreateWithFlags(&ev_fork, cudaEventDisableTiming);
        cudaEventCreateWithFlags(&ev_join, cudaEventDisableTiming);
    }

    // fork side stream off the (captured) legacy stream
    cudaEventRecord(ev_fork, 0);
    cudaStreamWaitEvent(s_side, ev_fork, 0);

    // side branch: bond -> s
    bond_kernel<<<ROWS_TOT / 16, 256, 0, s_side>>>(bond);
    s_kernel   <<<B_, 1024, 0, s_side>>>();
    cudaEventRecord(ev_join, s_side);

    // main branch: GEMM -> Y (independent of bond/s)
    fusedY_kernel<<<ROWS_TOT / 64, 256>>>(atom, adj, W);

    // join, then epilogue needs both Y and s
    cudaStreamWaitEvent(0, ev_join, 0);
    epilogue_kernel<<<ROWS_TOT * F_ / 1024, 256>>>(bias, out);
}

// round 12
// speedup vs baseline: 1.8073x; 1.0363x over previous
#include <cuda_runtime.h>
#include <cstdint>

#define B_   16
#define N_   1024
#define M_   12
#define FB_  32
#define F_   128
#define ROWS_TOT (B_ * N_)   // 16384

__device__ float g_p[ROWS_TOT];
__device__ float g_s[ROWS_TOT];
__device__ float g_Y[ROWS_TOT * F_];   // unscaled GEMM result (8 MB)

// ---------------------------------------------------------------------------
// Kernel 1 (proven): p[b,n] = prod_m r_m / max(sum_m r_m,eps)^12
// ---------------------------------------------------------------------------
__global__ void bond_kernel(const float* __restrict__ bond) {
    int warp = (blockIdx.x << 3) + (threadIdx.x >> 5);
    int lane = threadIdx.x & 31;
    int grp  = lane >> 3;
    int sub  = lane & 7;
    int row0 = warp << 1;
    const float* b0 = bond + (size_t)row0 * (M_ * FB_);
    const float* b1 = b0 + (M_ * FB_);

    float4 v0[3], v1[3];
#pragma unroll
    for (int i = 0; i < 3; ++i) {
        int off = (((i << 2) + grp) << 5) + (sub << 2);
        v0[i] = *(const float4*)(b0 + off);
        v1[i] = *(const float4*)(b1 + off);
    }

    float sum0 = 0.f, prod0 = 1.f, sum1 = 0.f, prod1 = 1.f;
#pragma unroll
    for (int i = 0; i < 3; ++i) {
        float s0 = v0[i].x*v0[i].x + v0[i].y*v0[i].y + v0[i].z*v0[i].z + v0[i].w*v0[i].w;
        float s1 = v1[i].x*v1[i].x + v1[i].y*v1[i].y + v1[i].z*v1[i].z + v1[i].w*v1[i].w;
#pragma unroll
        for (int off = 1; off <= 4; off <<= 1) {
            s0 += __shfl_xor_sync(0xffffffffu, s0, off);
            s1 += __shfl_xor_sync(0xffffffffu, s1, off);
        }
        float r0 = 1.0f / s0;          // (sqrt(s))^-2 == 1/s
        float r1 = 1.0f / s1;
        sum0 += r0; prod0 *= r0;
        sum1 += r1; prod1 *= r1;
    }
#pragma unroll
    for (int off = 8; off <= 16; off <<= 1) {
        sum0  += __shfl_xor_sync(0xffffffffu, sum0, off);
        sum1  += __shfl_xor_sync(0xffffffffu, sum1, off);
        prod0 *= __shfl_xor_sync(0xffffffffu, prod0, off);
        prod1 *= __shfl_xor_sync(0xffffffffu, prod1, off);
    }
    if (lane == 0) {
        float D  = fmaxf(sum0, 1e-12f);
        float d2 = D*D, d4 = d2*d2;
        g_p[row0] = prod0 / (d4*d4*d4);
    } else if (lane == 1) {
        float D  = fmaxf(sum1, 1e-12f);
        float d2 = D*D, d4 = d2*d2;
        g_p[row0 + 1] = prod1 / (d4*d4*d4);
    }
}

// ---------------------------------------------------------------------------
// Kernel 2 (proven): colsum over B, u = max(colsum,eps)/p, s = u / sum_n u
// ---------------------------------------------------------------------------
__global__ void s_kernel() {
    __shared__ float red[32];
    int b = blockIdx.x, n = threadIdx.x;
    int wid = n >> 5, lane = n & 31;

    float cs = 0.f;
#pragma unroll
    for (int bb = 0; bb < B_; ++bb) cs += g_p[bb * N_ + n];
    float u = fmaxf(cs, 1e-12f) / g_p[b * N_ + n];

    float v = u;
#pragma unroll
    for (int off = 16; off; off >>= 1) v += __shfl_xor_sync(0xffffffffu, v, off);
    if (lane == 0) red[wid] = v;
    __syncthreads();
    if (wid == 0) {
        float t = red[lane];
#pragma unroll
        for (int off = 16; off; off >>= 1) t += __shfl_xor_sync(0xffffffffu, t, off);
        if (lane == 0) red[0] = 1.0f / fmaxf(t, 1e-12f);
    }
    __syncthreads();
    g_s[b * N_ + n] = u * red[0];
}

// ---------------------------------------------------------------------------
// Kernel 3: pipelined gather + mean + GEMM -> Y.
//   256 blocks x 256 threads, 64 rows. Dynamic smem 96 KB:
//     sA [64][128] (32 KB)  — each warp writes/reads ONLY its own 8 rows
//     sW [128][128] (64 KB) — full W, staged once
//   ONE __syncthreads (after W stage). Warps pipeline gather vs FMA freely.
// ---------------------------------------------------------------------------
extern __shared__ float dsm[];

__global__ __launch_bounds__(256) void fusedY_kernel(
    const float* __restrict__ atom, const int* __restrict__ adj,
    const float* __restrict__ W)
{
    float (*sA)[F_] = (float(*)[F_])dsm;               // [64][128]
    float (*sW)[F_] = (float(*)[F_])(dsm + 64 * F_);   // [128][128]

    int tid  = threadIdx.x;
    int wid  = tid >> 5;
    int lane = tid & 31;
    int row0 = blockIdx.x << 6;

    // ---- Stage ALL of W once ----
    {
        const float4* src = (const float4*)W;
        float4* dst = (float4*)sW;
#pragma unroll
        for (int t = 0; t < 16; ++t) dst[tid + (t << 8)] = src[tid + (t << 8)];
    }
    __syncthreads();          // the only block-wide barrier

    // ---- Per-warp A build (own 8 rows only) ----
#pragma unroll
    for (int rr = 0; rr < 8; ++rr) {
        int r = (wid << 3) + rr;
        int g = row0 + r;
        int b = g >> 10;
        const float* arow  = atom + ((size_t)g << 7);
        const float* abase = atom + ((size_t)b << 17);
        int myidx = (lane < M_) ? adj[(size_t)g * M_ + lane] : 0;

        float4 self = *(const float4*)(arow + (lane << 2));
        float ax = 0.f, ay = 0.f, az = 0.f, aw = 0.f;
#pragma unroll
        for (int m = 0; m < M_; ++m) {
            int idx = __shfl_sync(0xffffffffu, myidx, m) & (N_ - 1);
            float4 nb = *(const float4*)(abase + ((size_t)idx << 7) + (lane << 2));
            ax += nb.x; ay += nb.y; az += nb.z; aw += nb.w;
        }
        const float inv12 = 1.0f / 12.0f;
        float4 av;
        av.x = self.x + ax * inv12;
        av.y = self.y + ay * inv12;
        av.z = self.z + az * inv12;
        av.w = self.w + aw * inv12;
        *(float4*)&sA[r][lane << 2] = av;
    }
    __syncwarp();             // intra-warp visibility of sA rows

    // ---- GEMM: 128 flat k iterations, no barriers ----
    unsigned long long acc[8][2];
#pragma unroll
    for (int r = 0; r < 8; ++r) { acc[r][0] = 0ull; acc[r][1] = 0ull; }

#pragma unroll 4
    for (int kk = 0; kk < F_; ++kk) {
        const unsigned long long* wp = (const unsigned long long*)&sW[kk][lane << 2];
        unsigned long long w01 = wp[0], w23 = wp[1];
#pragma unroll
        for (int r = 0; r < 8; ++r) {
            float a = sA[(wid << 3) + r][kk];            // warp-broadcast LDS
            unsigned long long a2;
            asm("mov.b64 %0, {%1, %1};" : "=l"(a2) : "f"(a));
            asm("fma.rn.f32x2 %0, %1, %2, %0;" : "+l"(acc[r][0]) : "l"(a2), "l"(w01));
            asm("fma.rn.f32x2 %0, %1, %2, %0;" : "+l"(acc[r][1]) : "l"(a2), "l"(w23));
        }
    }

    // ---- Write raw Y ----
#pragma unroll
    for (int r = 0; r < 8; ++r) {
        int g = row0 + (wid << 3) + r;
        float c0, c1, c2, c3;
        asm("mov.b64 {%0, %1}, %2;" : "=f"(c0), "=f"(c1) : "l"(acc[r][0]));
        asm("mov.b64 {%0, %1}, %2;" : "=f"(c2), "=f"(c3) : "l"(acc[r][1]));
        *(float4*)(g_Y + ((size_t)g << 7) + (lane << 2)) = make_float4(c0, c1, c2, c3);
    }
}

// ---------------------------------------------------------------------------
// Kernel 4: out = relu(s*Y + bias), 4 float4 per thread (MLP).
// ---------------------------------------------------------------------------
__global__ __launch_bounds__(256) void epilogue_kernel(
    const float* __restrict__ bias, float* __restrict__ out)
{
    int base = blockIdx.x * 1024 + threadIdx.x;    // float4 index space (524288)
    float4 y[4]; float s[4]; float4 bv[4];
#pragma unroll
    for (int i = 0; i < 4; ++i) {
        int idx = base + (i << 8);
        y[i]  = *(const float4*)(g_Y + ((size_t)idx << 2));
        s[i]  = g_s[idx >> 5];
        bv[i] = *(const float4*)(bias + ((idx & 31) << 2));
    }
#pragma unroll
    for (int i = 0; i < 4; ++i) {
        int idx = base + (i << 8);
        float4 o;
        o.x = fmaxf(fmaf(s[i], y[i].x, bv[i].x), 0.f);
        o.y = fmaxf(fmaf(s[i], y[i].y, bv[i].y), 0.f);
        o.z = fmaxf(fmaf(s[i], y[i].z, bv[i].z), 0.f);
        o.w = fmaxf(fmaf(s[i], y[i].w, bv[i].w), 0.f);
        *(float4*)(out + ((size_t)idx << 2)) = o;
    }
}

// ---------------------------------------------------------------------------
// Launch: fork-join graph.
//   legacy:  fusedY ────────────────┐
//   side:    bond → s ──────────────┤→ epilogue (legacy)
// ---------------------------------------------------------------------------
extern "C" void kernel_launch(void* const* d_in, const int* in_sizes, int n_in,
                              void* d_out, int out_size) {
    const float* atom = (const float*)d_in[0];
    const float* bond = (const float*)d_in[1];
    const int*   adj  = (const int*)d_in[2];
    const float* W    = (const float*)d_in[3];
    const float* bias = (const float*)d_in[4];
    float*       out  = (float*)d_out;

    static cudaStream_t s_side = nullptr;
    static cudaEvent_t  ev_fork = nullptr, ev_join = nullptr;
    if (!s_side) {
        cudaStreamCreateWithFlags(&s_side, cudaStreamNonBlocking);
        cudaEventCreateWithFlags(&ev_fork, cudaEventDisableTiming);
        cudaEventCreateWithFlags(&ev_join, cudaEventDisableTiming);
        cudaFuncSetAttribute(fusedY_kernel,
                             cudaFuncAttributeMaxDynamicSharedMemorySize, 98304);
    }

    // fork side stream off the (captured) legacy stream
    cudaEventRecord(ev_fork, 0);
    cudaStreamWaitEvent(s_side, ev_fork, 0);

    // side branch: bond -> s
    bond_kernel<<<ROWS_TOT / 16, 256, 0, s_side>>>(bond);
    s_kernel   <<<B_, 1024, 0, s_side>>>();
    cudaEventRecord(ev_join, s_side);

    // main branch: GEMM -> Y (independent of bond/s)
    fusedY_kernel<<<ROWS_TOT / 64, 256, 98304>>>(atom, adj, W);

    // join, then epilogue needs both Y and s
    cudaStreamWaitEvent(0, ev_join, 0);
    epilogue_kernel<<<512, 256>>>(bias, out);
}

// round 13
// speedup vs baseline: 1.8977x; 1.0501x over previous
#include <cuda_runtime.h>
#include <cstdint>

#define B_   16
#define N_   1024
#define M_   12
#define FB_  32
#define F_   128
#define ROWS_TOT (B_ * N_)   // 16384

__device__ float g_p[ROWS_TOT];
__device__ float g_s[ROWS_TOT];

// ---------------------------------------------------------------------------
// Kernel 1 (proven R4): p[b,n] = prod_m r_m / max(sum_m r_m,eps)^12
// One warp per TWO rows (6 independent LDG.128 per thread).
// ---------------------------------------------------------------------------
__global__ void bond_kernel(const float* __restrict__ bond) {
    int warp = (blockIdx.x << 3) + (threadIdx.x >> 5);
    int lane = threadIdx.x & 31;
    int grp  = lane >> 3;
    int sub  = lane & 7;
    int row0 = warp << 1;
    const float* b0 = bond + (size_t)row0 * (M_ * FB_);
    const float* b1 = b0 + (M_ * FB_);

    float4 v0[3], v1[3];
#pragma unroll
    for (int i = 0; i < 3; ++i) {
        int off = (((i << 2) + grp) << 5) + (sub << 2);
        v0[i] = *(const float4*)(b0 + off);
        v1[i] = *(const float4*)(b1 + off);
    }

    float sum0 = 0.f, prod0 = 1.f, sum1 = 0.f, prod1 = 1.f;
#pragma unroll
    for (int i = 0; i < 3; ++i) {
        float s0 = v0[i].x*v0[i].x + v0[i].y*v0[i].y + v0[i].z*v0[i].z + v0[i].w*v0[i].w;
        float s1 = v1[i].x*v1[i].x + v1[i].y*v1[i].y + v1[i].z*v1[i].z + v1[i].w*v1[i].w;
#pragma unroll
        for (int off = 1; off <= 4; off <<= 1) {
            s0 += __shfl_xor_sync(0xffffffffu, s0, off);
            s1 += __shfl_xor_sync(0xffffffffu, s1, off);
        }
        float r0 = 1.0f / s0;          // (sqrt(s))^-2 == 1/s
        float r1 = 1.0f / s1;
        sum0 += r0; prod0 *= r0;
        sum1 += r1; prod1 *= r1;
    }
#pragma unroll
    for (int off = 8; off <= 16; off <<= 1) {
        sum0  += __shfl_xor_sync(0xffffffffu, sum0, off);
        sum1  += __shfl_xor_sync(0xffffffffu, sum1, off);
        prod0 *= __shfl_xor_sync(0xffffffffu, prod0, off);
        prod1 *= __shfl_xor_sync(0xffffffffu, prod1, off);
    }
    if (lane == 0) {
        float D  = fmaxf(sum0, 1e-12f);
        float d2 = D*D, d4 = d2*d2;
        g_p[row0] = prod0 / (d4*d4*d4);
    } else if (lane == 1) {
        float D  = fmaxf(sum1, 1e-12f);
        float d2 = D*D, d4 = d2*d2;
        g_p[row0 + 1] = prod1 / (d4*d4*d4);
    }
}

// ---------------------------------------------------------------------------
// Kernel 2 (proven): colsum over B, u = max(colsum,eps)/p, s = u / sum_n u
// ---------------------------------------------------------------------------
__global__ void s_kernel() {
    __shared__ float red[32];
    int b = blockIdx.x, n = threadIdx.x;
    int wid = n >> 5, lane = n & 31;

    float cs = 0.f;
#pragma unroll
    for (int bb = 0; bb < B_; ++bb) cs += g_p[bb * N_ + n];
    float u = fmaxf(cs, 1e-12f) / g_p[b * N_ + n];

    float v = u;
#pragma unroll
    for (int off = 16; off; off >>= 1) v += __shfl_xor_sync(0xffffffffu, v, off);
    if (lane == 0) red[wid] = v;
    __syncthreads();
    if (wid == 0) {
        float t = red[lane];
#pragma unroll
        for (int off = 16; off; off >>= 1) t += __shfl_xor_sync(0xffffffffu, t, off);
        if (lane == 0) red[0] = 1.0f / fmaxf(t, 1e-12f);
    }
    __syncthreads();
    g_s[b * N_ + n] = u * red[0];
}

// ---------------------------------------------------------------------------
// Kernel 3: gather + mean + GEMM + s + bias + ReLU -> out (no Y detour).
//   256 blocks x 256 threads, 64 rows. Dynamic smem 96 KB:
//     sA [64][128] (32 KB)  — per-warp private 8 rows
//     sW [128][128] (64 KB) — full W, staged once
//   ONE __syncthreads. Inner loop: per 4 k's, A = one broadcast LDS.128 per
//   row (8 total), W = ulonglong2 per k (pairs pre-packed). Crossbar ~6cyc/k.
// ---------------------------------------------------------------------------
extern __shared__ float dsm[];

__global__ __launch_bounds__(256) void fused_kernel(
    const float* __restrict__ atom, const int* __restrict__ adj,
    const float* __restrict__ W, const float* __restrict__ bias,
    float* __restrict__ out)
{
    float (*sA)[F_] = (float(*)[F_])dsm;               // [64][128]
    float (*sW)[F_] = (float(*)[F_])(dsm + 64 * F_);   // [128][128]

    int tid  = threadIdx.x;
    int wid  = tid >> 5;
    int lane = tid & 31;
    int row0 = blockIdx.x << 6;

    // ---- Stage ALL of W once ----
    {
        const float4* src = (const float4*)W;
        float4* dst = (float4*)sW;
#pragma unroll
        for (int t = 0; t < 16; ++t) dst[tid + (t << 8)] = src[tid + (t << 8)];
    }
    __syncthreads();          // the only block-wide barrier

    // ---- Per-warp A build (own 8 rows only) ----
#pragma unroll
    for (int rr = 0; rr < 8; ++rr) {
        int r = (wid << 3) + rr;
        int g = row0 + r;
        int b = g >> 10;
        const float* arow  = atom + ((size_t)g << 7);
        const float* abase = atom + ((size_t)b << 17);
        int myidx = (lane < M_) ? adj[(size_t)g * M_ + lane] : 0;

        float4 self = *(const float4*)(arow + (lane << 2));
        float ax = 0.f, ay = 0.f, az = 0.f, aw = 0.f;
#pragma unroll
        for (int m = 0; m < M_; ++m) {
            int idx = __shfl_sync(0xffffffffu, myidx, m) & (N_ - 1);
            float4 nb = *(const float4*)(abase + ((size_t)idx << 7) + (lane << 2));
            ax += nb.x; ay += nb.y; az += nb.z; aw += nb.w;
        }
        const float inv12 = 1.0f / 12.0f;
        float4 av;
        av.x = self.x + ax * inv12;
        av.y = self.y + ay * inv12;
        av.z = self.z + az * inv12;
        av.w = self.w + aw * inv12;
        *(float4*)&sA[r][lane << 2] = av;
    }
    __syncwarp();             // intra-warp visibility of sA rows

    // ---- GEMM: 32 k-quads, amortized broadcast A, pre-packed W pairs ----
    unsigned long long acc[8][2];
#pragma unroll
    for (int r = 0; r < 8; ++r) { acc[r][0] = 0ull; acc[r][1] = 0ull; }

#pragma unroll 2
    for (int k4 = 0; k4 < 32; ++k4) {
        float a[8][4];
#pragma unroll
        for (int r = 0; r < 8; ++r)     // one broadcast LDS.128 per row
            *(float4*)a[r] = *(const float4*)&sA[(wid << 3) + r][k4 << 2];
#pragma unroll
        for (int q = 0; q < 4; ++q) {
            const ulonglong2 wv = *(const ulonglong2*)&sW[(k4 << 2) + q][lane << 2];
#pragma unroll
            for (int r = 0; r < 8; ++r) {
                unsigned long long a2;
                asm("mov.b64 %0, {%1, %1};" : "=l"(a2) : "f"(a[r][q]));
                asm("fma.rn.f32x2 %0, %1, %2, %0;" : "+l"(acc[r][0]) : "l"(a2), "l"(wv.x));
                asm("fma.rn.f32x2 %0, %1, %2, %0;" : "+l"(acc[r][1]) : "l"(a2), "l"(wv.y));
            }
        }
    }

    // ---- Tail: apply s, bias, ReLU; write out ----
    float4 bv = *(const float4*)(bias + (lane << 2));
#pragma unroll
    for (int r = 0; r < 8; ++r) {
        int g = row0 + (wid << 3) + r;
        float sc = g_s[g];
        float c0, c1, c2, c3;
        asm("mov.b64 {%0, %1}, %2;" : "=f"(c0), "=f"(c1) : "l"(acc[r][0]));
        asm("mov.b64 {%0, %1}, %2;" : "=f"(c2), "=f"(c3) : "l"(acc[r][1]));
        float4 o;
        o.x = fmaxf(fmaf(sc, c0, bv.x), 0.f);
        o.y = fmaxf(fmaf(sc, c1, bv.y), 0.f);
        o.z = fmaxf(fmaf(sc, c2, bv.z), 0.f);
        o.w = fmaxf(fmaf(sc, c3, bv.w), 0.f);
        *(float4*)(out + ((size_t)g << 7) + (lane << 2)) = o;
    }
}

// ---------------------------------------------------------------------------
extern "C" void kernel_launch(void* const* d_in, const int* in_sizes, int n_in,
                              void* d_out, int out_size) {
    const float* atom = (const float*)d_in[0];
    const float* bond = (const float*)d_in[1];
    const int*   adj  = (const int*)d_in[2];
    const float* W    = (const float*)d_in[3];
    const float* bias = (const float*)d_in[4];
    float*       out  = (float*)d_out;

    static bool init_done = false;
    if (!init_done) {
        cudaFuncSetAttribute(fused_kernel,
                             cudaFuncAttributeMaxDynamicSharedMemorySize, 98304);
        init_done = true;
    }

    bond_kernel <<<ROWS_TOT / 16, 256>>>(bond);
    s_kernel    <<<B_, 1024>>>();
    fused_kernel<<<ROWS_TOT / 64, 256, 98304>>>(atom, adj, W, bias, out);
}

// round 14
// speedup vs baseline: 1.9399x; 1.0222x over previous
#include <cuda_runtime.h>
#include <cstdint>

#define B_   16
#define N_   1024
#define M_   12
#define FB_  32
#define F_   128
#define ROWS_TOT (B_ * N_)   // 16384

__device__ float g_p[ROWS_TOT];
__device__ float g_s[ROWS_TOT];
__device__ int   g_done;     // s_kernel blocks arrive here (16 = ready)
__device__ int   g_fin;      // fused CTA completion counter (reset logic)

// ---------------------------------------------------------------------------
// Kernel 1 (proven R4): p[b,n] = prod_m r_m / max(sum_m r_m,eps)^12
// ---------------------------------------------------------------------------
__global__ void bond_kernel(const float* __restrict__ bond) {
    int warp = (blockIdx.x << 3) + (threadIdx.x >> 5);
    int lane = threadIdx.x & 31;
    int grp  = lane >> 3;
    int sub  = lane & 7;
    int row0 = warp << 1;
    const float* b0 = bond + (size_t)row0 * (M_ * FB_);
    const float* b1 = b0 + (M_ * FB_);

    float4 v0[3], v1[3];
#pragma unroll
    for (int i = 0; i < 3; ++i) {
        int off = (((i << 2) + grp) << 5) + (sub << 2);
        v0[i] = *(const float4*)(b0 + off);
        v1[i] = *(const float4*)(b1 + off);
    }

    float sum0 = 0.f, prod0 = 1.f, sum1 = 0.f, prod1 = 1.f;
#pragma unroll
    for (int i = 0; i < 3; ++i) {
        float s0 = v0[i].x*v0[i].x + v0[i].y*v0[i].y + v0[i].z*v0[i].z + v0[i].w*v0[i].w;
        float s1 = v1[i].x*v1[i].x + v1[i].y*v1[i].y + v1[i].z*v1[i].z + v1[i].w*v1[i].w;
#pragma unroll
        for (int off = 1; off <= 4; off <<= 1) {
            s0 += __shfl_xor_sync(0xffffffffu, s0, off);
            s1 += __shfl_xor_sync(0xffffffffu, s1, off);
        }
        float r0 = 1.0f / s0;          // (sqrt(s))^-2 == 1/s
        float r1 = 1.0f / s1;
        sum0 += r0; prod0 *= r0;
        sum1 += r1; prod1 *= r1;
    }
#pragma unroll
    for (int off = 8; off <= 16; off <<= 1) {
        sum0  += __shfl_xor_sync(0xffffffffu, sum0, off);
        sum1  += __shfl_xor_sync(0xffffffffu, sum1, off);
        prod0 *= __shfl_xor_sync(0xffffffffu, prod0, off);
        prod1 *= __shfl_xor_sync(0xffffffffu, prod1, off);
    }
    if (lane == 0) {
        float D  = fmaxf(sum0, 1e-12f);
        float d2 = D*D, d4 = d2*d2;
        g_p[row0] = prod0 / (d4*d4*d4);
    } else if (lane == 1) {
        float D  = fmaxf(sum1, 1e-12f);
        float d2 = D*D, d4 = d2*d2;
        g_p[row0 + 1] = prod1 / (d4*d4*d4);
    }
}

// ---------------------------------------------------------------------------
// Kernel 2: colsum over B, u = max(colsum,eps)/p, s = u / sum_n u.
// Each block signals readiness via release-atomic on g_done.
// ---------------------------------------------------------------------------
__global__ void s_kernel() {
    __shared__ float red[32];
    int b = blockIdx.x, n = threadIdx.x;
    int wid = n >> 5, lane = n & 31;

    float cs = 0.f;
#pragma unroll
    for (int bb = 0; bb < B_; ++bb) cs += g_p[bb * N_ + n];
    float u = fmaxf(cs, 1e-12f) / g_p[b * N_ + n];

    float v = u;
#pragma unroll
    for (int off = 16; off; off >>= 1) v += __shfl_xor_sync(0xffffffffu, v, off);
    if (lane == 0) red[wid] = v;
    __syncthreads();
    if (wid == 0) {
        float t = red[lane];
#pragma unroll
        for (int off = 16; off; off >>= 1) t += __shfl_xor_sync(0xffffffffu, t, off);
        if (lane == 0) red[0] = 1.0f / fmaxf(t, 1e-12f);
    }
    __syncthreads();
    g_s[b * N_ + n] = u * red[0];
    __syncthreads();                       // all of this block's g_s written
    if (n == 0) {
        __threadfence();                   // release g_s
        atomicAdd(&g_done, 1);
    }
}

// ---------------------------------------------------------------------------
// Kernel 3: gather + mean + GEMM; tail spin-waits for s, then s+bias+ReLU.
//   256 blocks x 256 threads, 64 rows. 96 KB smem (sA 32 + full sW 64).
//   A-build FIRST so its gather LDGs overlap W staging's L2 latency.
// ---------------------------------------------------------------------------
extern __shared__ float dsm[];

__global__ __launch_bounds__(256) void fused_kernel(
    const float* __restrict__ atom, const int* __restrict__ adj,
    const float* __restrict__ W, const float* __restrict__ bias,
    float* __restrict__ out)
{
    float (*sA)[F_] = (float(*)[F_])dsm;               // [64][128]
    float (*sW)[F_] = (float(*)[F_])(dsm + 64 * F_);   // [128][128]

    int tid  = threadIdx.x;
    int wid  = tid >> 5;
    int lane = tid & 31;
    int row0 = blockIdx.x << 6;

    // ---- Per-warp A build (own 8 rows only) ----
#pragma unroll
    for (int rr = 0; rr < 8; ++rr) {
        int r = (wid << 3) + rr;
        int g = row0 + r;
        int b = g >> 10;
        const float* arow  = atom + ((size_t)g << 7);
        const float* abase = atom + ((size_t)b << 17);
        int myidx = (lane < M_) ? adj[(size_t)g * M_ + lane] : 0;

        float4 self = *(const float4*)(arow + (lane << 2));
        float ax = 0.f, ay = 0.f, az = 0.f, aw = 0.f;
#pragma unroll
        for (int m = 0; m < M_; ++m) {
            int idx = __shfl_sync(0xffffffffu, myidx, m) & (N_ - 1);
            float4 nb = *(const float4*)(abase + ((size_t)idx << 7) + (lane << 2));
            ax += nb.x; ay += nb.y; az += nb.z; aw += nb.w;
        }
        const float inv12 = 1.0f / 12.0f;
        float4 av;
        av.x = self.x + ax * inv12;
        av.y = self.y + ay * inv12;
        av.z = self.z + az * inv12;
        av.w = self.w + aw * inv12;
        *(float4*)&sA[r][lane << 2] = av;
    }

    // ---- Stage ALL of W (overlaps tail of gather traffic) ----
    {
        const float4* src = (const float4*)W;
        float4* dst = (float4*)sW;
#pragma unroll
        for (int t = 0; t < 16; ++t) dst[tid + (t << 8)] = src[tid + (t << 8)];
    }
    __syncthreads();          // covers sW for all, sA per-warp implicitly

    // ---- GEMM: 32 k-quads ----
    unsigned long long acc[8][2];
#pragma unroll
    for (int r = 0; r < 8; ++r) { acc[r][0] = 0ull; acc[r][1] = 0ull; }

#pragma unroll 2
    for (int k4 = 0; k4 < 32; ++k4) {
        float a[8][4];
#pragma unroll
        for (int r = 0; r < 8; ++r)     // one broadcast LDS.128 per row
            *(float4*)a[r] = *(const float4*)&sA[(wid << 3) + r][k4 << 2];
#pragma unroll
        for (int q = 0; q < 4; ++q) {
            const ulonglong2 wv = *(const ulonglong2*)&sW[(k4 << 2) + q][lane << 2];
#pragma unroll
            for (int r = 0; r < 8; ++r) {
                unsigned long long a2;
                asm("mov.b64 %0, {%1, %1};" : "=l"(a2) : "f"(a[r][q]));
                asm("fma.rn.f32x2 %0, %1, %2, %0;" : "+l"(acc[r][0]) : "l"(a2), "l"(wv.x));
                asm("fma.rn.f32x2 %0, %1, %2, %0;" : "+l"(acc[r][1]) : "l"(a2), "l"(wv.y));
            }
        }
    }

    // ---- Wait for s (normally already available) ----
    if (tid == 0) {
        int d;
        do {
            asm volatile("ld.acquire.gpu.s32 %0, [%1];"
                         : "=r"(d) : "l"(&g_done) : "memory");
            if (d < B_) __nanosleep(64);
        } while (d < B_);
    }
    __syncthreads();

    // ---- Tail: apply s, bias, ReLU; write out ----
    float4 bv = *(const float4*)(bias + (lane << 2));
#pragma unroll
    for (int r = 0; r < 8; ++r) {
        int g = row0 + (wid << 3) + r;
        float sc = g_s[g];
        float c0, c1, c2, c3;
        asm("mov.b64 {%0, %1}, %2;" : "=f"(c0), "=f"(c1) : "l"(acc[r][0]));
        asm("mov.b64 {%0, %1}, %2;" : "=f"(c2), "=f"(c3) : "l"(acc[r][1]));
        float4 o;
        o.x = fmaxf(fmaf(sc, c0, bv.x), 0.f);
        o.y = fmaxf(fmaf(sc, c1, bv.y), 0.f);
        o.z = fmaxf(fmaf(sc, c2, bv.z), 0.f);
        o.w = fmaxf(fmaf(sc, c3, bv.w), 0.f);
        *(float4*)(out + ((size_t)g << 7) + (lane << 2)) = o;
    }

    // ---- Replay-safe flag reset: last CTA clears counters ----
    __syncthreads();
    if (tid == 0) {
        __threadfence();
        int f = atomicAdd(&g_fin, 1);
        if (f == (ROWS_TOT / 64) - 1) {       // last of 256 CTAs
            atomicExch(&g_done, 0);
            atomicExch(&g_fin, 0);
        }
    }
}

// ---------------------------------------------------------------------------
// Launch: bond→s on side stream (no edge into fused); fused spins for s.
// Side branch joined to legacy AFTER fused launch (capture-legal, no dep).
// ---------------------------------------------------------------------------
extern "C" void kernel_launch(void* const* d_in, const int* in_sizes, int n_in,
                              void* d_out, int out_size) {
    const float* atom = (const float*)d_in[0];
    const float* bond = (const float*)d_in[1];
    const int*   adj  = (const int*)d_in[2];
    const float* W    = (const float*)d_in[3];
    const float* bias = (const float*)d_in[4];
    float*       out  = (float*)d_out;

    static cudaStream_t s_side = nullptr;
    static cudaEvent_t  ev_fork = nullptr, ev_join = nullptr;
    if (!s_side) {
        cudaStreamCreateWithFlags(&s_side, cudaStreamNonBlocking);
        cudaEventCreateWithFlags(&ev_fork, cudaEventDisableTiming);
        cudaEventCreateWithFlags(&ev_join, cudaEventDisableTiming);
        cudaFuncSetAttribute(fused_kernel,
                             cudaFuncAttributeMaxDynamicSharedMemorySize, 98304);
    }

    cudaEventRecord(ev_fork, 0);
    cudaStreamWaitEvent(s_side, ev_fork, 0);

    bond_kernel<<<ROWS_TOT / 16, 256, 0, s_side>>>(bond);
    s_kernel   <<<B_, 1024, 0, s_side>>>();
    cudaEventRecord(ev_join, s_side);

    fused_kernel<<<ROWS_TOT / 64, 256, 98304>>>(atom, adj, W, bias, out);

    // join side branch (placed AFTER fused: no dependency, capture-legal)
    cudaStreamWaitEvent(0, ev_join, 0);
}